// round 8
// baseline (speedup 1.0000x reference)
#include <cuda_runtime.h>
#include <cuda_fp16.h>

#define NN 50000
#define NE 800000
#define FEAT 128
#define HID 64
#define NCLS 12
#define SB 49                         // scan blocks (1024 nodes each)

// ---------------- scratch (static device globals; zero-initialized) ----------
__device__ __align__(16) int     g_deg[NN];                  // zero-invariant
__device__ __align__(16) unsigned long long g_state[SB];     // zero-invariant
__device__ __align__(16) int     g_rowptr[NN + 1];
__device__ __align__(16) int     g_cursor[NN];
__device__ __align__(16) int     g_csr[NE];
__device__ __align__(16) float   g_dinv[NN];
__device__ __align__(16) __half2 g_xws[NN * (HID / 2)];  // (A@W)*dinv fp16, 128B/row
__device__ __align__(16) __half2 g_h1[NN * (HID / 2)];   // layer-1 activations (fp16)
__device__ __align__(16) __half  g_w1t[64 * FEAT];       // W1^T fp16 (n-major)
__device__ __align__(16) __half  g_w2t[64 * HID];        // W2^T fp16 (n-major)

// ---------------- CSR build + weight conversion ------------------------------
__global__ void k_count(const int* __restrict__ dst,
                        const float* __restrict__ W1, const float* __restrict__ W2) {
    int b = blockIdx.x;
    if (b == gridDim.x - 1) {            // extra block: convert weights to fp16 n-major
        for (int i = threadIdx.x; i < 64 * FEAT; i += 256) {
            int n = i / FEAT, k = i % FEAT;
            g_w1t[i] = __float2half(W1[k * 64 + n]);
        }
        for (int i = threadIdx.x; i < 64 * HID; i += 256) {
            int n = i / HID, k = i % HID;
            g_w2t[i] = __float2half(W2[k * 64 + n]);
        }
        return;
    }
    int e = b * 256 + threadIdx.x;
    if (e < NE) atomicAdd(&g_deg[dst[e]], 1);
}

__device__ __forceinline__ int block_excl_scan(int v, int* sm32) {
    int lane = threadIdx.x & 31, wid = threadIdx.x >> 5;
    int incl = v;
#pragma unroll
    for (int d = 1; d < 32; d <<= 1) {
        int n = __shfl_up_sync(0xffffffffu, incl, d);
        if (lane >= d) incl += n;
    }
    if (lane == 31) sm32[wid] = incl;
    __syncthreads();
    if (wid == 0) {
        int w = sm32[lane];
#pragma unroll
        for (int d = 1; d < 32; d <<= 1) {
            int n = __shfl_up_sync(0xffffffffu, w, d);
            if (lane >= d) w += n;
        }
        sm32[lane] = w;
    }
    __syncthreads();
    int off = wid ? sm32[wid - 1] : 0;
    return incl - v + off;
}

// single-pass scan via decoupled aggregates
__global__ void __launch_bounds__(1024)
k_scan() {
    __shared__ int sm32[32];
    __shared__ int s_base;
    int tid = threadIdx.x, b = blockIdx.x;
    int i = b * 1024 + tid;
    int v = (i < NN) ? g_deg[i] : 0;
    int excl = block_excl_scan(v, sm32);
    if (tid == 1023) {
        unsigned long long st = (1ULL << 32) | (unsigned)(excl + v);
        atomicExch(&g_state[b], st);
    }
    if (tid < 32) {
        unsigned sum = 0;
        for (int j = tid; j < b; j += 32) {
            unsigned long long s;
            do { s = atomicAdd(&g_state[j], 0ULL); } while (!(s >> 32));
            sum += (unsigned)s;
        }
#pragma unroll
        for (int d = 16; d; d >>= 1) sum += __shfl_xor_sync(0xffffffffu, sum, d);
        if (tid == 0) s_base = (int)sum;
    }
    __syncthreads();
    if (i < NN) {
        int run = s_base + excl;
        g_rowptr[i] = run;
        g_cursor[i] = run;
        g_dinv[i]   = rsqrtf((float)v + 1.0f);
    }
    if (b == 0 && tid == 0) g_rowptr[NN] = NE;
}

// fill CSR; restore zero-invariants for the next replay
__global__ void k_fill(const int* __restrict__ src,
                       const int* __restrict__ dst) {
    int e = blockIdx.x * blockDim.x + threadIdx.x;
    if (e < NN) g_deg[e] = 0;
    if (e < SB) g_state[e] = 0ULL;
    if (e < NE) {
        int d = dst[e];
        int pos = atomicAdd(&g_cursor[d], 1);
        g_csr[pos] = src[e];
    }
}

// ---------------- tensor-core GEMM ------------------------------------------
// C[NN,64] = A[NN,K] @ W[K,64]; epilogue *dinv[row] -> g_xws fp16.
// B fragments register-resident from fp16 n-major W^T in global; A via ldmatrix.
__device__ __forceinline__ void mma16816(float c[4],
                                         unsigned a0, unsigned a1, unsigned a2, unsigned a3,
                                         unsigned b0, unsigned b1) {
    asm volatile(
        "mma.sync.aligned.m16n8k16.row.col.f32.f16.f16.f32 "
        "{%0,%1,%2,%3}, {%4,%5,%6,%7}, {%8,%9}, {%0,%1,%2,%3};\n"
        : "+f"(c[0]), "+f"(c[1]), "+f"(c[2]), "+f"(c[3])
        : "r"(a0), "r"(a1), "r"(a2), "r"(a3), "r"(b0), "r"(b1));
}

__device__ __forceinline__ void ldsm4(unsigned& a0, unsigned& a1,
                                      unsigned& a2, unsigned& a3, unsigned addr) {
    asm volatile(
        "ldmatrix.sync.aligned.m8n8.x4.shared.b16 {%0,%1,%2,%3}, [%4];\n"
        : "=r"(a0), "=r"(a1), "=r"(a2), "=r"(a3) : "r"(addr));
}

template <int K, bool A_FROM_H1>
__global__ void __launch_bounds__(256)
k_gemm(const float* __restrict__ Aext) {
    const int KP = 64 + 8;              // Ah row pitch (halfs)
    __shared__ __half Ah[64 * KP];
    int tid = threadIdx.x;
    int lane = tid & 31, warp = tid >> 5;
    int row0 = blockIdx.x * 64;
    int gid = lane >> 2, tig = lane & 3;
    int n0 = warp * 8;
    const __half* Wt = (K == FEAT) ? g_w1t : g_w2t;

    // B fragments: registers, loaded once (L2/L1-cached; same 8KB per block)
    const int NK = K / 16;
    unsigned bf[NK][2];
#pragma unroll
    for (int kk = 0; kk < NK; kk++) {
        const __half* wb = &Wt[(n0 + gid) * K + kk * 16 + tig * 2];
        bf[kk][0] = *(const unsigned*)wb;
        bf[kk][1] = *(const unsigned*)(wb + 8);
    }

    float cacc[4][4];
#pragma unroll
    for (int r = 0; r < 4; r++)
        cacc[r][0] = cacc[r][1] = cacc[r][2] = cacc[r][3] = 0.f;

    const int NCH = K / 64;
    float4  vf[4];
    unsigned vh[8];

    // prefetch chunk 0
    if (A_FROM_H1) {
#pragma unroll
        for (int p = 0; p < 8; p++) {
            int i = tid + p * 256;
            int r = i >> 5, c = i & 31;
            vh[p] = (row0 + r < NN) ? *(const unsigned*)&g_h1[(row0 + r) * 32 + c] : 0u;
        }
    } else {
#pragma unroll
        for (int p = 0; p < 4; p++) {
            int i = tid + p * 256;
            int r = i >> 4, c4 = i & 15;
            vf[p] = (row0 + r < NN)
                ? *(const float4*)&Aext[(size_t)(row0 + r) * K + c4 * 4]
                : make_float4(0.f, 0.f, 0.f, 0.f);
        }
    }

    // ldmatrix lane address: row = lane&15, k-offset = (lane>>4)*8
    unsigned abase = (unsigned)__cvta_generic_to_shared(
        &Ah[(lane & 15) * KP + (lane >> 4) * 8]);

#pragma unroll
    for (int ch = 0; ch < NCH; ch++) {
        if (A_FROM_H1) {
#pragma unroll
            for (int p = 0; p < 8; p++) {
                int i = tid + p * 256;
                int r = i >> 5, c = i & 31;
                *(unsigned*)&Ah[r * KP + c * 2] = vh[p];
            }
        } else {
#pragma unroll
            for (int p = 0; p < 4; p++) {
                int i = tid + p * 256;
                int r = i >> 4, c4 = i & 15;
                __half2 h0 = __floats2half2_rn(vf[p].x, vf[p].y);
                __half2 h1 = __floats2half2_rn(vf[p].z, vf[p].w);
                *(unsigned*)&Ah[r * KP + c4 * 4]     = *(unsigned*)&h0;
                *(unsigned*)&Ah[r * KP + c4 * 4 + 2] = *(unsigned*)&h1;
            }
        }
        __syncthreads();

        if (!A_FROM_H1 && ch + 1 < NCH) {
#pragma unroll
            for (int p = 0; p < 4; p++) {
                int i = tid + p * 256;
                int r = i >> 4, c4 = i & 15;
                vf[p] = (row0 + r < NN)
                    ? *(const float4*)&Aext[(size_t)(row0 + r) * K + (ch + 1) * 64 + c4 * 4]
                    : make_float4(0.f, 0.f, 0.f, 0.f);
            }
        }

#pragma unroll
        for (int kk = 0; kk < 4; kk++) {
            int kf = ch * 4 + kk;          // b-fragment index
            int kl = kk * 16;              // k offset in Ah
#pragma unroll
            for (int rt = 0; rt < 4; rt++) {
                unsigned a0, a1, a2, a3;
                ldsm4(a0, a1, a2, a3,
                      abase + (unsigned)((rt * 16 * KP + kl) * sizeof(__half)));
                mma16816(cacc[rt], a0, a1, a2, a3, bf[kf][0], bf[kf][1]);
            }
        }
        if (ch + 1 < NCH) __syncthreads();
    }

#pragma unroll
    for (int rt = 0; rt < 4; rt++) {
        int r0 = row0 + rt * 16 + gid;
        int r1 = r0 + 8;
        if (r0 < NN) {
            float dv = g_dinv[r0];
            g_xws[r0 * 32 + n0 / 2 + tig] =
                __floats2half2_rn(cacc[rt][0] * dv, cacc[rt][1] * dv);
        }
        if (r1 < NN) {
            float dv = g_dinv[r1];
            g_xws[r1 * 32 + n0 / 2 + tig] =
                __floats2half2_rn(cacc[rt][2] * dv, cacc[rt][3] * dv);
        }
    }
}

// ---------------- aggregation: warp per dst node ----------------------------
__device__ __forceinline__ void agg_row(int node, int lane, float& a0, float& a1) {
    int beg = g_rowptr[node];
    int end = g_rowptr[node + 1];
    a0 = 0.f; a1 = 0.f;
    for (int base = beg; base < end; base += 32) {
        int idx = base + lane;
        int s_l = (idx < end) ? g_csr[idx] : 0;
        int iters = end - base;
        if (iters > 32) iters = 32;
#pragma unroll 4
        for (int j = 0; j < iters; j++) {
            int s = __shfl_sync(0xffffffffu, s_l, j);
            float2 v = __half22float2(g_xws[s * (HID / 2) + lane]);
            a0 += v.x;
            a1 += v.y;
        }
    }
}

__global__ void k_agg1(const float* __restrict__ b1) {
    int warp = (blockIdx.x * blockDim.x + threadIdx.x) >> 5;
    int lane = threadIdx.x & 31;
    if (warp >= NN) return;
    float a0, a1;
    agg_row(warp, lane, a0, a1);
    float dd = g_dinv[warp];
    float2 sv = __half22float2(g_xws[warp * (HID / 2) + lane]);
    float r0 = fmaxf(fmaf(dd, a0 + sv.x, b1[2 * lane + 0]), 0.f);
    float r1 = fmaxf(fmaf(dd, a1 + sv.y, b1[2 * lane + 1]), 0.f);
    g_h1[warp * (HID / 2) + lane] = __floats2half2_rn(r0, r1);
}

__global__ void k_agg2(const float* __restrict__ b2, const float* __restrict__ Wfc,
                       const float* __restrict__ bfc, float* __restrict__ out) {
    __shared__ float sW[HID * NCLS];
    __shared__ float sb2[HID];
    __shared__ float sbfc[NCLS];
    int tid = threadIdx.x;
    for (int i = tid; i < HID * NCLS; i += 256) sW[i] = Wfc[i];
    if (tid < HID)  sb2[tid]  = b2[tid];
    if (tid < NCLS) sbfc[tid] = bfc[tid];
    __syncthreads();

    int warp = (blockIdx.x * blockDim.x + tid) >> 5;
    int lane = tid & 31;
    if (warp >= NN) return;
    float a0, a1;
    agg_row(warp, lane, a0, a1);
    float dd = g_dinv[warp];
    float2 sv = __half22float2(g_xws[warp * (HID / 2) + lane]);
    float t0 = fmaxf(fmaf(dd, a0 + sv.x, sb2[2 * lane + 0]), 0.f);
    float t1 = fmaxf(fmaf(dd, a1 + sv.y, sb2[2 * lane + 1]), 0.f);

    float res = 0.f;
#pragma unroll
    for (int c = 0; c < NCLS; c++) {
        float p = t0 * sW[(2 * lane + 0) * NCLS + c] + t1 * sW[(2 * lane + 1) * NCLS + c];
        p += __shfl_xor_sync(0xffffffffu, p, 16);
        p += __shfl_xor_sync(0xffffffffu, p, 8);
        p += __shfl_xor_sync(0xffffffffu, p, 4);
        p += __shfl_xor_sync(0xffffffffu, p, 2);
        p += __shfl_xor_sync(0xffffffffu, p, 1);
        if (lane == c) res = p + sbfc[c];
    }
    if (lane < NCLS) out[warp * NCLS + lane] = res;
}

// ---------------- launch -----------------------------------------------------
extern "C" void kernel_launch(void* const* d_in, const int* in_sizes, int n_in,
                              void* d_out, int out_size) {
    const float* x   = (const float*)d_in[0];
    const int*   ei  = (const int*)d_in[1];   // int32 (JAX x64-disabled)
    const float* W1  = (const float*)d_in[2];
    const float* b1  = (const float*)d_in[3];
    const float* W2  = (const float*)d_in[4];
    const float* b2  = (const float*)d_in[5];
    const float* Wfc = (const float*)d_in[6];
    const float* bfc = (const float*)d_in[7];
    float* out = (float*)d_out;
    const int* srcp = ei;
    const int* dstp = ei + NE;

    k_count<<<(NE + 255) / 256 + 1, 256>>>(dstp, W1, W2);   // count + W->fp16
    k_scan<<<SB, 1024>>>();
    k_fill<<<(NE + 255) / 256, 256>>>(srcp, dstp);

    k_gemm<FEAT, false><<<(NN + 63) / 64, 256>>>(x);        // -> g_xws (fp16)
    k_agg1<<<(NN + 7) / 8, 256>>>(b1);                       // -> g_h1 (fp16)
    k_gemm<HID, true><<<(NN + 63) / 64, 256>>>(nullptr);     // -> g_xws (fp16)
    k_agg2<<<(NN + 7) / 8, 256>>>(b2, Wfc, bfc, out);        // -> d_out
}